// round 7
// baseline (speedup 1.0000x reference)
#include <cuda_runtime.h>
#include <math.h>
#include <cstdint>

#define BB   8192
#define DVV  768
#define NE   8
#define DD   1024
#define GG   2048

// GEMM tiling: CTA 128x256, 8 warps of 64x64, BK=32, 3-stage cp.async
#define BM 128
#define BN 256
#define BK 32
#define STAGES 3
#define PADK 40                       // floats per smem row (conflict-free LDS.64)
#define STAGE_FLOATS ((BM + BN) * PADK)
#define SMEM_BYTES (STAGES * STAGE_FLOATS * 4)

// K-permutation within each 8-float group: logical g -> physical
// 0,4,1,5,2,6,3,7  (so logical pair (c, c+4) is physically adjacent)
__host__ __device__ __forceinline__ int kperm(int k) {
    int g = k & 7;
    return (k & ~7) | ((g < 4) ? (g << 1) : (((g - 4) << 1) | 1));
}

// ---------------------------------------------------------------------------
// Scratch (static device globals).  All GEMM K-operands stored k-permuted.
// ---------------------------------------------------------------------------
__device__ float g_inr[(size_t)2 * BB * DVV];     // [z][B][768] rna, k-perm
__device__ float g_pwT[(size_t)2 * DVV * DD];     // [z][N=1024][K=768] k-perm
__device__ float g_pbias[2 * DD];
__device__ float g_w1T[(size_t)NE * GG * DD];     // [e][n][k=GG] k-perm
__device__ float g_w2T[(size_t)NE * DD * DD];     // [e][n][k=DD] k-perm
__device__ float g_combined[(size_t)BB * GG];     // k-perm columns
__device__ float g_gate[BB * NE];
__device__ float g_h[(size_t)BB * NE * DD];       // k-perm columns
__device__ float g_t[(size_t)BB * NE * DD];       // normal layout
__device__ float g_out_dummy;

// ---------------------------------------------------------------------------
// Helpers
// ---------------------------------------------------------------------------
__device__ __forceinline__ float rna_tf32(float x) {
    uint32_t u;
    asm("cvt.rna.tf32.f32 %0, %1;" : "=r"(u) : "f"(x));
    return __uint_as_float(u);
}
__device__ __forceinline__ uint32_t smem_u32(const void* p) {
    uint32_t a;
    asm("{ .reg .u64 t; cvta.to.shared.u64 t, %1; cvt.u32.u64 %0, t; }" : "=r"(a) : "l"(p));
    return a;
}
__device__ __forceinline__ void cp_async16(uint32_t dst, const float* src) {
    asm volatile("cp.async.cg.shared.global [%0], [%1], 16;" :: "r"(dst), "l"(src));
}
#define CP_COMMIT() asm volatile("cp.async.commit_group;" ::: "memory")
#define CP_WAIT(n)  asm volatile("cp.async.wait_group %0;" :: "n"(n) : "memory")

__device__ __forceinline__ void mma_tf32(float& c0, float& c1, float& c2, float& c3,
                                         uint32_t a0, uint32_t a1, uint32_t a2, uint32_t a3,
                                         uint32_t b0, uint32_t b1) {
    asm volatile(
        "mma.sync.aligned.m16n8k8.row.col.f32.tf32.tf32.f32 "
        "{%0,%1,%2,%3}, {%4,%5,%6,%7}, {%8,%9}, {%0,%1,%2,%3};\n"
        : "+f"(c0), "+f"(c1), "+f"(c2), "+f"(c3)
        : "r"(a0), "r"(a1), "r"(a2), "r"(a3), "r"(b0), "r"(b1));
}

// ---------------------------------------------------------------------------
// tf32 tensor-core GEMM: C[m,n] = act( sum_k A[m,k]*B[n,k] + bias[n] )
// A [M,K] row-major k-permuted, B [N,K] K-major k-permuted (both rna).
// CTA 128x256, warp grid 2(m) x 4(n), warp tile 64x64, 3-stage cp.async.
// Fragment loads are LDS.64 thanks to the k-permutation.
// mode 0: store rna(v) to k-permuted columns       (proj -> combined)
// mode 1: store rna(gelu(v)) to k-permuted columns (gemm1 -> h)
// mode 2: store v, normal columns                  (gemm2 -> t)
// ---------------------------------------------------------------------------
__global__ __launch_bounds__(256, 1)
void tf32_gemm(const float* __restrict__ A, long aBatch, int lda,
               const float* __restrict__ B, long bBatch, int ldb,
               const float* __restrict__ bias, long biasBatch,
               int K, int mode,
               float* __restrict__ C, long cBatch, int ldc,
               int colOfs, int colStride)
{
    extern __shared__ float smem[];
    const int tid  = threadIdx.x;
    const int wid  = tid >> 5;
    const int lane = tid & 31;
    const int e    = blockIdx.z;
    const int blockRow = blockIdx.y * BM;
    const int blockCol = blockIdx.x * BN;

    A    += (long)e * aBatch;
    B    += (long)e * bBatch;
    bias += (long)e * biasBatch;
    C    += (long)e * cBatch;
    const int cOfs = colOfs + e * colStride;

    const float* Ag = A + (long)blockRow * lda;
    const float* Bg = B + (long)blockCol * ldb;

    const uint32_t smem_base = smem_u32(smem);

    // warp grid: 2 (m) x 4 (n); warp tile 64x64
    const int warpRow = (wid & 1) * 64;
    const int warpCol = (wid >> 1) * 64;
    const int groupID = lane >> 2;
    const int ctig    = lane & 3;

    float acc[4][8][4];
    #pragma unroll
    for (int i = 0; i < 4; i++)
        #pragma unroll
        for (int j = 0; j < 8; j++)
            #pragma unroll
            for (int r = 0; r < 4; r++) acc[i][j][r] = 0.0f;

    const int NC = K / BK;

    // stage loader: A 1024 chunks (4/thr) + B 2048 chunks (8/thr), 16B each
    auto load_stage = [&](int stage, int chunk) {
        const int k0 = chunk * BK;
        const uint32_t aBase = smem_base + (uint32_t)(stage * STAGE_FLOATS) * 4u;
        const uint32_t bBase = aBase + (uint32_t)(BM * PADK) * 4u;
        #pragma unroll
        for (int i = 0; i < 4; i++) {
            int id = tid + i * 256;
            int m = id >> 3, kc = id & 7;
            cp_async16(aBase + (uint32_t)(m * PADK + kc * 4) * 4u,
                       Ag + (long)m * lda + k0 + kc * 4);
        }
        #pragma unroll
        for (int i = 0; i < 8; i++) {
            int id = tid + i * 256;
            int n = id >> 3, kc = id & 7;
            cp_async16(bBase + (uint32_t)(n * PADK + kc * 4) * 4u,
                       Bg + (long)n * ldb + k0 + kc * 4);
        }
        CP_COMMIT();
    };

    #pragma unroll
    for (int s = 0; s < STAGES - 1; s++) load_stage(s, s);
    CP_WAIT(STAGES - 2);
    __syncthreads();

    for (int c = 0; c < NC; c++) {
        if (c + STAGES - 1 < NC)
            load_stage((c + STAGES - 1) % STAGES, c + STAGES - 1);

        const int stage = c % STAGES;
        const uint32_t* As = reinterpret_cast<const uint32_t*>(smem + stage * STAGE_FLOATS);
        const uint32_t* Bs = As + BM * PADK;

        #pragma unroll
        for (int kk = 0; kk < 4; kk++) {
            const int kb = kk * 8 + 2 * ctig;
            uint2 av0[4], av1[4], bv[8];
            #pragma unroll
            for (int i = 0; i < 4; i++) {
                const uint32_t* p = As + (warpRow + i * 16 + groupID) * PADK + kb;
                av0[i] = *reinterpret_cast<const uint2*>(p);             // (a0, a2)
                av1[i] = *reinterpret_cast<const uint2*>(p + 8 * PADK);  // (a1, a3)
            }
            #pragma unroll
            for (int j = 0; j < 8; j++) {
                const uint32_t* p = Bs + (warpCol + j * 8 + groupID) * PADK + kb;
                bv[j] = *reinterpret_cast<const uint2*>(p);              // (b0, b1)
            }
            #pragma unroll
            for (int i = 0; i < 4; i++)
                #pragma unroll
                for (int j = 0; j < 8; j++)
                    mma_tf32(acc[i][j][0], acc[i][j][1], acc[i][j][2], acc[i][j][3],
                             av0[i].x, av1[i].x, av0[i].y, av1[i].y,
                             bv[j].x, bv[j].y);
        }

        CP_WAIT(STAGES - 2);
        __syncthreads();
    }

    // ---- epilogue ----
    #pragma unroll
    for (int i = 0; i < 4; i++) {
        const int r0 = blockRow + warpRow + i * 16 + groupID;
        #pragma unroll
        for (int j = 0; j < 8; j++) {
            const int gc = blockCol + warpCol + j * 8 + ctig * 2;
            const float b0 = bias[gc], b1 = bias[gc + 1];
            float v0 = acc[i][j][0] + b0;
            float v1 = acc[i][j][1] + b1;
            float v2 = acc[i][j][2] + b0;
            float v3 = acc[i][j][3] + b1;
            if (mode == 2) {
                float* c0p = C + (long)r0 * ldc + cOfs + gc;
                float* c1p = C + (long)(r0 + 8) * ldc + cOfs + gc;
                *reinterpret_cast<float2*>(c0p) = make_float2(v0, v1);
                *reinterpret_cast<float2*>(c1p) = make_float2(v2, v3);
            } else {
                if (mode == 1) {
                    v0 = 0.5f * v0 * (1.0f + erff(v0 * 0.70710678118654752f));
                    v1 = 0.5f * v1 * (1.0f + erff(v1 * 0.70710678118654752f));
                    v2 = 0.5f * v2 * (1.0f + erff(v2 * 0.70710678118654752f));
                    v3 = 0.5f * v3 * (1.0f + erff(v3 * 0.70710678118654752f));
                }
                // store to k-permuted columns (feeds the next GEMM's A)
                const int cp0 = kperm(cOfs + gc);   // kperm(c+1) == kperm(c)+2
                float* c0p = C + (long)r0 * ldc + cp0;
                float* c1p = C + (long)(r0 + 8) * ldc + cp0;
                c0p[0] = rna_tf32(v0); c0p[2] = rna_tf32(v1);
                c1p[0] = rna_tf32(v2); c1p[2] = rna_tf32(v3);
            }
        }
    }
}

// ---------------------------------------------------------------------------
// Fused prep: rna-round both inputs into g_inr (k-permuted), pack proj biases
// Each thread handles 4 consecutive logical k within one 8-group.
// ---------------------------------------------------------------------------
__global__ void prep_round_kernel(const float* __restrict__ visual,
                                  const float* __restrict__ text,
                                  const float* __restrict__ vis_b,
                                  const float* __restrict__ txt_b,
                                  float* __restrict__ inr,
                                  float* __restrict__ pbias)
{
    const long nPer = (long)BB * DVV;
    long t = (long)blockIdx.x * blockDim.x + threadIdx.x;
    if (t < 2 * DD)
        pbias[t] = (t < DD) ? vis_b[t] : txt_b[t - DD];
    long i = t * 4;
    if (i >= 2 * nPer) return;
    const float* src = (i < nPer) ? (visual + i) : (text + (i - nPer));
    float4 v = *reinterpret_cast<const float4*>(src);
    long base = i & ~7L;
    int  off  = (int)(i & 4) ? 1 : 0;    // g=0..3 -> even slots, g=4..7 -> odd
    inr[base + off + 0] = rna_tf32(v.x);
    inr[base + off + 2] = rna_tf32(v.y);
    inr[base + off + 4] = rna_tf32(v.z);
    inr[base + off + 6] = rna_tf32(v.w);
}

// ---------------------------------------------------------------------------
// W [K,N] -> WT [N,K] rna-rounded, K k-permuted; z selects source
// ---------------------------------------------------------------------------
__global__ __launch_bounds__(256)
void transpose_round_kernel(const float* __restrict__ W0,
                            const float* __restrict__ W1,
                            float* __restrict__ WT, int K, int N)
{
    __shared__ float tile[32][33];
    const int e = blockIdx.z;
    const float* W = (W1 == nullptr) ? (W0 + (long)e * K * N)
                                     : (e == 0 ? W0 : W1);
    float* WTe = WT + (long)e * K * N;
    const int n0 = blockIdx.x * 32, k0 = blockIdx.y * 32;
    const int tx = threadIdx.x & 31, ty = threadIdx.x >> 5;

    #pragma unroll
    for (int r = 0; r < 4; r++)
        tile[ty + r * 8][tx] = W[(long)(k0 + ty + r * 8) * N + n0 + tx];
    __syncthreads();
    #pragma unroll
    for (int r = 0; r < 4; r++) {
        int n = n0 + ty + r * 8, k = k0 + tx;
        WTe[(long)n * K + kperm(k)] = rna_tf32(tile[tx][ty + r * 8]);
    }
}

// ---------------------------------------------------------------------------
// Gate: one warp per row (combined is k-permuted; gw indexed logically)
// ---------------------------------------------------------------------------
__global__ void gate_kernel(const float* __restrict__ combined,
                            const float* __restrict__ gw,
                            const float* __restrict__ gb,
                            float* __restrict__ gate)
{
    int warp = (blockIdx.x * blockDim.x + threadIdx.x) >> 5;
    int lane = threadIdx.x & 31;
    if (warp >= BB) return;
    const float* row = combined + (long)warp * GG;

    float acc[NE];
    #pragma unroll
    for (int e = 0; e < NE; e++) acc[e] = 0.0f;

    for (int k = lane; k < GG; k += 32) {
        float x = row[kperm(k)];
        const float4 w0 = *reinterpret_cast<const float4*>(gw + (long)k * NE);
        const float4 w1 = *reinterpret_cast<const float4*>(gw + (long)k * NE + 4);
        acc[0] = fmaf(x, w0.x, acc[0]);
        acc[1] = fmaf(x, w0.y, acc[1]);
        acc[2] = fmaf(x, w0.z, acc[2]);
        acc[3] = fmaf(x, w0.w, acc[3]);
        acc[4] = fmaf(x, w1.x, acc[4]);
        acc[5] = fmaf(x, w1.y, acc[5]);
        acc[6] = fmaf(x, w1.z, acc[6]);
        acc[7] = fmaf(x, w1.w, acc[7]);
    }
    #pragma unroll
    for (int e = 0; e < NE; e++)
        #pragma unroll
        for (int o = 16; o > 0; o >>= 1)
            acc[e] += __shfl_xor_sync(0xFFFFFFFFu, acc[e], o);

    float m = -1e30f;
    #pragma unroll
    for (int e = 0; e < NE; e++) { acc[e] += gb[e]; m = fmaxf(m, acc[e]); }
    float s = 0.0f;
    #pragma unroll
    for (int e = 0; e < NE; e++) { acc[e] = expf(acc[e] - m); s += acc[e]; }
    float inv = 1.0f / s;
    if (lane < NE) gate[(long)warp * NE + lane] = acc[lane] * inv;
}

// ---------------------------------------------------------------------------
// LayerNorm per (b,e) row + gated reduction over experts (t is normal layout)
// ---------------------------------------------------------------------------
__global__ __launch_bounds__(256)
void ln_reduce_kernel(const float* __restrict__ t,
                      const float* __restrict__ gate,
                      const float* __restrict__ ln_g,
                      const float* __restrict__ ln_b,
                      float* __restrict__ out)
{
    const int b = blockIdx.x;
    const int tid = threadIdx.x;
    const int wid = tid >> 5, lane = tid & 31;

    __shared__ float sm_s[8];
    __shared__ float sm_ss[8];

    float o[4] = {0.f, 0.f, 0.f, 0.f};

    for (int e = 0; e < NE; e++) {
        const float* row = t + ((long)b * NE + e) * DD;
        float4 x = *reinterpret_cast<const float4*>(row + tid * 4);
        float s  = x.x + x.y + x.z + x.w;
        float ss = x.x * x.x + x.y * x.y + x.z * x.z + x.w * x.w;
        #pragma unroll
        for (int o2 = 16; o2 > 0; o2 >>= 1) {
            s  += __shfl_xor_sync(0xFFFFFFFFu, s, o2);
            ss += __shfl_xor_sync(0xFFFFFFFFu, ss, o2);
        }
        if (lane == 0) { sm_s[wid] = s; sm_ss[wid] = ss; }
        __syncthreads();
        float ts = 0.f, tss = 0.f;
        #pragma unroll
        for (int w = 0; w < 8; w++) { ts += sm_s[w]; tss += sm_ss[w]; }
        __syncthreads();

        float mu   = ts * (1.0f / DD);
        float var  = tss * (1.0f / DD) - mu * mu;
        float rstd = rsqrtf(var + 1e-5f);
        float p    = gate[(long)b * NE + e];

        const float4 g4 = *reinterpret_cast<const float4*>(ln_g + (long)e * DD + tid * 4);
        const float4 b4 = *reinterpret_cast<const float4*>(ln_b + (long)e * DD + tid * 4);
        const float* xv = &x.x;
        const float* gv = &g4.x;
        const float* bv = &b4.x;
        #pragma unroll
        for (int j = 0; j < 4; j++) {
            float n = (xv[j] - mu) * rstd;
            o[j] = fmaf(p, fmaf(n, gv[j], bv[j]), o[j]);
        }
    }
    *reinterpret_cast<float4*>(out + (long)b * DD + tid * 4) =
        make_float4(o[0], o[1], o[2], o[3]);
}

// ---------------------------------------------------------------------------
// Launch.  The 4th launch is the projection GEMM (the one ncu captures).
// ---------------------------------------------------------------------------
extern "C" void kernel_launch(void* const* d_in, const int* in_sizes, int n_in,
                              void* d_out, int out_size)
{
    const float* visual = (const float*)d_in[0];
    const float* text   = (const float*)d_in[1];
    const float* vis_w  = (const float*)d_in[2];
    const float* vis_b  = (const float*)d_in[3];
    const float* txt_w  = (const float*)d_in[4];
    const float* txt_b  = (const float*)d_in[5];
    const float* gate_w = (const float*)d_in[6];
    const float* gate_b = (const float*)d_in[7];
    const float* w1     = (const float*)d_in[8];
    const float* b1     = (const float*)d_in[9];
    const float* w2     = (const float*)d_in[10];
    const float* b2     = (const float*)d_in[11];
    const float* ln_g   = (const float*)d_in[12];
    const float* ln_b   = (const float*)d_in[13];
    float* out = (float*)d_out;

    float *inr, *pwT, *pbias, *w1T, *w2T, *combined, *gate, *h, *t;
    cudaGetSymbolAddress((void**)&inr, g_inr);
    cudaGetSymbolAddress((void**)&pwT, g_pwT);
    cudaGetSymbolAddress((void**)&pbias, g_pbias);
    cudaGetSymbolAddress((void**)&w1T, g_w1T);
    cudaGetSymbolAddress((void**)&w2T, g_w2T);
    cudaGetSymbolAddress((void**)&combined, g_combined);
    cudaGetSymbolAddress((void**)&gate, g_gate);
    cudaGetSymbolAddress((void**)&h, g_h);
    cudaGetSymbolAddress((void**)&t, g_t);

    cudaFuncSetAttribute(tf32_gemm, cudaFuncAttributeMaxDynamicSharedMemorySize, SMEM_BYTES);

    // 1) w1 transpose (no deps)
    transpose_round_kernel<<<dim3(DD/32, GG/32, NE), 256>>>(w1, nullptr, w1T, GG, DD);
    // 2) proj weights transpose
    transpose_round_kernel<<<dim3(DD/32, DVV/32, 2), 256>>>(vis_w, txt_w, pwT, DVV, DD);
    // 3) input rounding + bias pack
    {
        long n = 2L * BB * DVV;
        int blocks = (int)((n / 4 + 255) / 256);
        prep_round_kernel<<<blocks, 256>>>(visual, text, vis_b, txt_b, inr, pbias);
    }
    // 4) batched projection (z=2) -> combined [8192, 2048]  *** profiled ***
    {
        dim3 g(DD / BN, BB / BM, 2);
        tf32_gemm<<<g, 256, SMEM_BYTES>>>(inr, (long)BB * DVV, DVV,
                                          pwT, (long)DVV * DD, DVV,
                                          pbias, DD, DVV, 0,
                                          combined, 0, GG, 0, DD);
    }
    // 5) expert GEMM1 + GELU -> h
    {
        dim3 g(DD / BN, BB / BM, NE);
        tf32_gemm<<<g, 256, SMEM_BYTES>>>(combined, 0, GG,
                                          w1T, (long)GG * DD, GG,
                                          b1, DD, GG, 1,
                                          h, DD, NE * DD, 0, 0);
    }
    // 6) w2 transpose
    transpose_round_kernel<<<dim3(DD/32, DD/32, NE), 256>>>(w2, nullptr, w2T, DD, DD);
    // 7) gate softmax
    gate_kernel<<<(BB * 32) / 256, 256>>>(combined, gate_w, gate_b, gate);
    // 8) expert GEMM2 -> t
    {
        dim3 g(DD / BN, BB / BM, NE);
        tf32_gemm<<<g, 256, SMEM_BYTES>>>(h, DD, NE * DD,
                                          w2T, (long)DD * DD, DD,
                                          b2, DD, DD, 2,
                                          t, DD, NE * DD, 0, 0);
    }
    // 9) LayerNorm + gated reduce -> out
    ln_reduce_kernel<<<BB, 256>>>(t, gate, ln_g, ln_b, out);
}

// round 8
// speedup vs baseline: 2.4946x; 2.4946x over previous
#include <cuda_runtime.h>
#include <cuda_fp16.h>
#include <math.h>
#include <cstdint>

#define BB   8192
#define DVV  768
#define NE   8
#define DD   1024
#define GG   2048

// GEMM tiling: CTA 128x256, 8 warps of 64x64, BK=64 halves, 3-stage cp.async
#define BM 128
#define BN 256
#define BK 64
#define STAGES 3
#define PADH 80                         // halves per smem row (row shift = 8 banks)
#define STAGE_HALVES ((BM + BN) * PADH)
#define SMEM_BYTES (STAGES * STAGE_HALVES * 2)

// K-permutation within each 16-group: pair order [0,4,1,5,2,6,3,7]
// so logical pairs (2c,2c+1) and (8+2c,8+2c+1) are physically adjacent (8B).
__host__ __device__ __forceinline__ int kperm16(int k) {
    int g = k & 15, p = g >> 1, b = g & 1;
    int q = (p < 4) ? (p << 1) : (((p - 4) << 1) | 1);
    return (k & ~15) | (q << 1) | b;
}

// ---------------------------------------------------------------------------
// Scratch (static device globals). GEMM operands stored as k-permuted fp16.
// ---------------------------------------------------------------------------
__device__ __half g_inr[(size_t)2 * BB * DVV];
__device__ __half g_pwT[(size_t)2 * DVV * DD];
__device__ float  g_pbias[2 * DD];
__device__ __half g_w1T[(size_t)NE * GG * DD];
__device__ __half g_w2T[(size_t)NE * DD * DD];
__device__ __half g_combined[(size_t)BB * GG];
__device__ float  g_gate[BB * NE];
__device__ __half g_h[(size_t)BB * NE * DD];
__device__ float  g_t[(size_t)BB * NE * DD];

// ---------------------------------------------------------------------------
// Helpers
// ---------------------------------------------------------------------------
__device__ __forceinline__ uint32_t smem_u32(const void* p) {
    uint32_t a;
    asm("{ .reg .u64 t; cvta.to.shared.u64 t, %1; cvt.u32.u64 %0, t; }" : "=r"(a) : "l"(p));
    return a;
}
__device__ __forceinline__ void cp_async16(uint32_t dst, const void* src) {
    asm volatile("cp.async.cg.shared.global [%0], [%1], 16;" :: "r"(dst), "l"(src));
}
#define CP_COMMIT() asm volatile("cp.async.commit_group;" ::: "memory")
#define CP_WAIT(n)  asm volatile("cp.async.wait_group %0;" :: "n"(n) : "memory")

__device__ __forceinline__ void mma_f16(float& c0, float& c1, float& c2, float& c3,
                                        uint32_t a0, uint32_t a1, uint32_t a2, uint32_t a3,
                                        uint32_t b0, uint32_t b1) {
    asm volatile(
        "mma.sync.aligned.m16n8k16.row.col.f32.f16.f16.f32 "
        "{%0,%1,%2,%3}, {%4,%5,%6,%7}, {%8,%9}, {%0,%1,%2,%3};\n"
        : "+f"(c0), "+f"(c1), "+f"(c2), "+f"(c3)
        : "r"(a0), "r"(a1), "r"(a2), "r"(a3), "r"(b0), "r"(b1));
}

// ---------------------------------------------------------------------------
// fp16 tensor-core GEMM: C[m,n] = act( sum_k A[m,k]*B[n,k] + bias[n] )
// A [M,K] row-major, B [N,K] K-major, both k-permuted fp16.
// CTA 128x256, warp grid 2(m) x 4(n), warp tile 64x64, 3-stage cp.async.
// mode 0: store half(v) k-permuted cols     (proj -> combined)
// mode 1: store half(gelu(v)) k-perm cols   (gemm1 -> h)
// mode 2: store fp32 v, normal cols         (gemm2 -> t)
// ---------------------------------------------------------------------------
__global__ __launch_bounds__(256, 1)
void f16_gemm(const __half* __restrict__ A, long aBatch, int lda,
              const __half* __restrict__ B, long bBatch, int ldb,
              const float* __restrict__ bias, long biasBatch,
              int K, int mode,
              float* __restrict__ Cf, __half* __restrict__ Ch,
              long cBatch, int ldc, int colOfs, int colStride)
{
    extern __shared__ __half smem[];
    const int tid  = threadIdx.x;
    const int wid  = tid >> 5;
    const int lane = tid & 31;
    const int e    = blockIdx.z;
    const int blockRow = blockIdx.y * BM;
    const int blockCol = blockIdx.x * BN;

    A    += (long)e * aBatch;
    B    += (long)e * bBatch;
    bias += (long)e * biasBatch;
    if (Cf) Cf += (long)e * cBatch;
    if (Ch) Ch += (long)e * cBatch;
    const int cOfs = colOfs + e * colStride;

    const __half* Ag = A + (long)blockRow * lda;
    const __half* Bg = B + (long)blockCol * ldb;

    const uint32_t smem_base = smem_u32(smem);

    // warp grid: 2 (m) x 4 (n); warp tile 64x64
    const int warpRow = (wid & 1) * 64;
    const int warpCol = (wid >> 1) * 64;
    const int groupID = lane >> 2;
    const int ctig    = lane & 3;

    float acc[4][8][4];
    #pragma unroll
    for (int i = 0; i < 4; i++)
        #pragma unroll
        for (int j = 0; j < 8; j++)
            #pragma unroll
            for (int r = 0; r < 4; r++) acc[i][j][r] = 0.0f;

    const int NC = K / BK;

    // stage loader: A 1024 16B-chunks (4/thr) + B 2048 (8/thr)
    auto load_stage = [&](int stage, int chunk) {
        const int k0 = chunk * BK;
        const uint32_t aBase = smem_base + (uint32_t)(stage * STAGE_HALVES) * 2u;
        const uint32_t bBase = aBase + (uint32_t)(BM * PADH) * 2u;
        #pragma unroll
        for (int i = 0; i < 4; i++) {
            int id = tid + i * 256;
            int m = id >> 3, kc = id & 7;
            cp_async16(aBase + (uint32_t)(m * PADH + kc * 8) * 2u,
                       Ag + (long)m * lda + k0 + kc * 8);
        }
        #pragma unroll
        for (int i = 0; i < 8; i++) {
            int id = tid + i * 256;
            int n = id >> 3, kc = id & 7;
            cp_async16(bBase + (uint32_t)(n * PADH + kc * 8) * 2u,
                       Bg + (long)n * ldb + k0 + kc * 8);
        }
        CP_COMMIT();
    };

    #pragma unroll
    for (int s = 0; s < STAGES - 1; s++) load_stage(s, s);
    CP_WAIT(STAGES - 2);
    __syncthreads();

    for (int c = 0; c < NC; c++) {
        if (c + STAGES - 1 < NC)
            load_stage((c + STAGES - 1) % STAGES, c + STAGES - 1);

        const int stage = c % STAGES;
        const __half* As = smem + stage * STAGE_HALVES;
        const __half* Bs = As + BM * PADH;

        #pragma unroll
        for (int kk = 0; kk < 4; kk++) {
            const int kb = kk * 16 + 4 * ctig;     // halves within row
            uint2 av0[4], av1[4];
            #pragma unroll
            for (int i = 0; i < 4; i++) {
                const __half* p = As + (warpRow + i * 16 + groupID) * PADH + kb;
                av0[i] = *reinterpret_cast<const uint2*>(p);            // (a0,a2)
                av1[i] = *reinterpret_cast<const uint2*>(p + 8 * PADH); // (a1,a3)
            }
            #pragma unroll
            for (int j = 0; j < 8; j++) {
                const __half* p = Bs + (warpCol + j * 8 + groupID) * PADH + kb;
                uint2 bv = *reinterpret_cast<const uint2*>(p);          // (b0,b1)
                #pragma unroll
                for (int i = 0; i < 4; i++)
                    mma_f16(acc[i][j][0], acc[i][j][1], acc[i][j][2], acc[i][j][3],
                            av0[i].x, av1[i].x, av0[i].y, av1[i].y,
                            bv.x, bv.y);
            }
        }

        CP_WAIT(STAGES - 2);
        __syncthreads();
    }

    // ---- epilogue ----
    #pragma unroll
    for (int i = 0; i < 4; i++) {
        const int r0 = blockRow + warpRow + i * 16 + groupID;
        #pragma unroll
        for (int j = 0; j < 8; j++) {
            const int gc = blockCol + warpCol + j * 8 + ctig * 2;
            const float b0 = bias[gc], b1 = bias[gc + 1];
            float v0 = acc[i][j][0] + b0;
            float v1 = acc[i][j][1] + b1;
            float v2 = acc[i][j][2] + b0;
            float v3 = acc[i][j][3] + b1;
            if (mode == 2) {
                float* c0p = Cf + (long)r0 * ldc + cOfs + gc;
                float* c1p = Cf + (long)(r0 + 8) * ldc + cOfs + gc;
                *reinterpret_cast<float2*>(c0p) = make_float2(v0, v1);
                *reinterpret_cast<float2*>(c1p) = make_float2(v2, v3);
            } else {
                if (mode == 1) {
                    v0 = 0.5f * v0 * (1.0f + erff(v0 * 0.70710678118654752f));
                    v1 = 0.5f * v1 * (1.0f + erff(v1 * 0.70710678118654752f));
                    v2 = 0.5f * v2 * (1.0f + erff(v2 * 0.70710678118654752f));
                    v3 = 0.5f * v3 * (1.0f + erff(v3 * 0.70710678118654752f));
                }
                const int cp0 = kperm16(cOfs + gc);   // even; pair stays adjacent
                *reinterpret_cast<__half2*>(Ch + (long)r0 * ldc + cp0) =
                    __floats2half2_rn(v0, v1);
                *reinterpret_cast<__half2*>(Ch + (long)(r0 + 8) * ldc + cp0) =
                    __floats2half2_rn(v2, v3);
            }
        }
    }
}

// ---------------------------------------------------------------------------
// Fused prep: convert both inputs to k-permuted fp16, pack proj biases.
// One thread = one 16-element k-group (64B read, 32B write).
// ---------------------------------------------------------------------------
__global__ void prep_kernel(const float* __restrict__ visual,
                            const float* __restrict__ text,
                            const float* __restrict__ vis_b,
                            const float* __restrict__ txt_b,
                            __half* __restrict__ inr,
                            float* __restrict__ pbias)
{
    const long nPer = (long)BB * DVV;
    long t = (long)blockIdx.x * blockDim.x + threadIdx.x;
    if (t < 2 * DD)
        pbias[t] = (t < DD) ? vis_b[t] : txt_b[t - DD];
    long i = t * 16;
    if (i >= 2 * nPer) return;
    const float* src = (i < nPer) ? (visual + i) : (text + (i - nPer));
    float4 v0 = *reinterpret_cast<const float4*>(src + 0);
    float4 v1 = *reinterpret_cast<const float4*>(src + 4);
    float4 v2 = *reinterpret_cast<const float4*>(src + 8);
    float4 v3 = *reinterpret_cast<const float4*>(src + 12);
    __half2 o[8];
    o[0] = __floats2half2_rn(v0.x, v0.y);   // k0,1
    o[1] = __floats2half2_rn(v2.x, v2.y);   // k8,9
    o[2] = __floats2half2_rn(v0.z, v0.w);   // k2,3
    o[3] = __floats2half2_rn(v2.z, v2.w);   // k10,11
    o[4] = __floats2half2_rn(v1.x, v1.y);   // k4,5
    o[5] = __floats2half2_rn(v3.x, v3.y);   // k12,13
    o[6] = __floats2half2_rn(v1.z, v1.w);   // k6,7
    o[7] = __floats2half2_rn(v3.z, v3.w);   // k14,15
    *reinterpret_cast<uint4*>(inr + i)     = *reinterpret_cast<uint4*>(&o[0]);
    *reinterpret_cast<uint4*>(inr + i + 8) = *reinterpret_cast<uint4*>(&o[4]);
}

// ---------------------------------------------------------------------------
// W [K,N] fp32 -> WT [N,K] fp16 k-permuted; z selects source
// ---------------------------------------------------------------------------
__global__ __launch_bounds__(256)
void transpose_kernel(const float* __restrict__ W0,
                      const float* __restrict__ W1,
                      __half* __restrict__ WT, int K, int N)
{
    __shared__ float tile[32][33];
    const int e = blockIdx.z;
    const float* W = (W1 == nullptr) ? (W0 + (long)e * K * N)
                                     : (e == 0 ? W0 : W1);
    __half* WTe = WT + (long)e * K * N;
    const int n0 = blockIdx.x * 32, k0 = blockIdx.y * 32;
    const int tx = threadIdx.x & 31, ty = threadIdx.x >> 5;

    #pragma unroll
    for (int r = 0; r < 4; r++)
        tile[ty + r * 8][tx] = W[(long)(k0 + ty + r * 8) * N + n0 + tx];
    __syncthreads();
    #pragma unroll
    for (int r = 0; r < 4; r++) {
        int n = n0 + ty + r * 8, k = k0 + tx;
        WTe[(long)n * K + kperm16(k)] = __float2half_rn(tile[tx][ty + r * 8]);
    }
}

// ---------------------------------------------------------------------------
// Gate: one warp per row (combined fp16 k-permuted; gw logical index)
// ---------------------------------------------------------------------------
__global__ void gate_kernel(const __half* __restrict__ combined,
                            const float* __restrict__ gw,
                            const float* __restrict__ gb,
                            float* __restrict__ gate)
{
    int warp = (blockIdx.x * blockDim.x + threadIdx.x) >> 5;
    int lane = threadIdx.x & 31;
    if (warp >= BB) return;
    const __half* row = combined + (long)warp * GG;

    float acc[NE];
    #pragma unroll
    for (int e = 0; e < NE; e++) acc[e] = 0.0f;

    for (int k = lane; k < GG; k += 32) {
        float x = __half2float(row[kperm16(k)]);
        const float4 w0 = *reinterpret_cast<const float4*>(gw + (long)k * NE);
        const float4 w1 = *reinterpret_cast<const float4*>(gw + (long)k * NE + 4);
        acc[0] = fmaf(x, w0.x, acc[0]);
        acc[1] = fmaf(x, w0.y, acc[1]);
        acc[2] = fmaf(x, w0.z, acc[2]);
        acc[3] = fmaf(x, w0.w, acc[3]);
        acc[4] = fmaf(x, w1.x, acc[4]);
        acc[5] = fmaf(x, w1.y, acc[5]);
        acc[6] = fmaf(x, w1.z, acc[6]);
        acc[7] = fmaf(x, w1.w, acc[7]);
    }
    #pragma unroll
    for (int e = 0; e < NE; e++)
        #pragma unroll
        for (int o = 16; o > 0; o >>= 1)
            acc[e] += __shfl_xor_sync(0xFFFFFFFFu, acc[e], o);

    float m = -1e30f;
    #pragma unroll
    for (int e = 0; e < NE; e++) { acc[e] += gb[e]; m = fmaxf(m, acc[e]); }
    float s = 0.0f;
    #pragma unroll
    for (int e = 0; e < NE; e++) { acc[e] = expf(acc[e] - m); s += acc[e]; }
    float inv = 1.0f / s;
    if (lane < NE) gate[(long)warp * NE + lane] = acc[lane] * inv;
}

// ---------------------------------------------------------------------------
// LayerNorm per (b,e) row + gated reduction over experts (t fp32, normal)
// ---------------------------------------------------------------------------
__global__ __launch_bounds__(256)
void ln_reduce_kernel(const float* __restrict__ t,
                      const float* __restrict__ gate,
                      const float* __restrict__ ln_g,
                      const float* __restrict__ ln_b,
                      float* __restrict__ out)
{
    const int b = blockIdx.x;
    const int tid = threadIdx.x;
    const int wid = tid >> 5, lane = tid & 31;

    __shared__ float sm_s[8];
    __shared__ float sm_ss[8];

    float o[4] = {0.f, 0.f, 0.f, 0.f};

    for (int e = 0; e < NE; e++) {
        const float* row = t + ((long)b * NE + e) * DD;
        float4 x = *reinterpret_cast<const float4*>(row + tid * 4);
        float s  = x.x + x.y + x.z + x.w;
        float ss = x.x * x.x + x.y * x.y + x.z * x.z + x.w * x.w;
        #pragma unroll
        for (int o2 = 16; o2 > 0; o2 >>= 1) {
            s  += __shfl_xor_sync(0xFFFFFFFFu, s, o2);
            ss += __shfl_xor_sync(0xFFFFFFFFu, ss, o2);
        }
        if (lane == 0) { sm_s[wid] = s; sm_ss[wid] = ss; }
        __syncthreads();
        float ts = 0.f, tss = 0.f;
        #pragma unroll
        for (int w = 0; w < 8; w++) { ts += sm_s[w]; tss += sm_ss[w]; }
        __syncthreads();

        float mu   = ts * (1.0f / DD);
        float var  = tss * (1.0f / DD) - mu * mu;
        float rstd = rsqrtf(var + 1e-5f);
        float p    = gate[(long)b * NE + e];

        const float4 g4 = *reinterpret_cast<const float4*>(ln_g + (long)e * DD + tid * 4);
        const float4 b4 = *reinterpret_cast<const float4*>(ln_b + (long)e * DD + tid * 4);
        const float* xv = &x.x;
        const float* gv = &g4.x;
        const float* bv = &b4.x;
        #pragma unroll
        for (int j = 0; j < 4; j++) {
            float n = (xv[j] - mu) * rstd;
            o[j] = fmaf(p, fmaf(n, gv[j], bv[j]), o[j]);
        }
    }
    *reinterpret_cast<float4*>(out + (long)b * DD + tid * 4) =
        make_float4(o[0], o[1], o[2], o[3]);
}

// ---------------------------------------------------------------------------
// Launch.  The 4th launch is the projection GEMM (the one ncu captures).
// ---------------------------------------------------------------------------
extern "C" void kernel_launch(void* const* d_in, const int* in_sizes, int n_in,
                              void* d_out, int out_size)
{
    const float* visual = (const float*)d_in[0];
    const float* text   = (const float*)d_in[1];
    const float* vis_w  = (const float*)d_in[2];
    const float* vis_b  = (const float*)d_in[3];
    const float* txt_w  = (const float*)d_in[4];
    const float* txt_b  = (const float*)d_in[5];
    const float* gate_w = (const float*)d_in[6];
    const float* gate_b = (const float*)d_in[7];
    const float* w1     = (const float*)d_in[8];
    const float* b1     = (const float*)d_in[9];
    const float* w2     = (const float*)d_in[10];
    const float* b2     = (const float*)d_in[11];
    const float* ln_g   = (const float*)d_in[12];
    const float* ln_b   = (const float*)d_in[13];
    float* out = (float*)d_out;

    __half *inr, *pwT, *w1T, *w2T, *combined, *h;
    float *pbias, *gate, *t;
    cudaGetSymbolAddress((void**)&inr, g_inr);
    cudaGetSymbolAddress((void**)&pwT, g_pwT);
    cudaGetSymbolAddress((void**)&pbias, g_pbias);
    cudaGetSymbolAddress((void**)&w1T, g_w1T);
    cudaGetSymbolAddress((void**)&w2T, g_w2T);
    cudaGetSymbolAddress((void**)&combined, g_combined);
    cudaGetSymbolAddress((void**)&gate, g_gate);
    cudaGetSymbolAddress((void**)&h, g_h);
    cudaGetSymbolAddress((void**)&t, g_t);

    cudaFuncSetAttribute(f16_gemm, cudaFuncAttributeMaxDynamicSharedMemorySize, SMEM_BYTES);

    // 1) w1 transpose (no deps)
    transpose_kernel<<<dim3(DD/32, GG/32, NE), 256>>>(w1, nullptr, w1T, GG, DD);
    // 2) proj weights transpose
    transpose_kernel<<<dim3(DD/32, DVV/32, 2), 256>>>(vis_w, txt_w, pwT, DVV, DD);
    // 3) input conversion + bias pack
    {
        long n = 2L * BB * DVV;
        int blocks = (int)((n / 16 + 255) / 256);
        prep_kernel<<<blocks, 256>>>(visual, text, vis_b, txt_b, inr, pbias);
    }
    // 4) batched projection (z=2) -> combined [8192, 2048]  *** profiled ***
    {
        dim3 g(DD / BN, BB / BM, 2);
        f16_gemm<<<g, 256, SMEM_BYTES>>>(inr, (long)BB * DVV, DVV,
                                         pwT, (long)DVV * DD, DVV,
                                         pbias, DD, DVV, 0,
                                         nullptr, combined, 0, GG, 0, DD);
    }
    // 5) expert GEMM1 + GELU -> h
    {
        dim3 g(DD / BN, BB / BM, NE);
        f16_gemm<<<g, 256, SMEM_BYTES>>>(combined, 0, GG,
                                         w1T, (long)GG * DD, GG,
                                         b1, DD, GG, 1,
                                         nullptr, h, DD, NE * DD, 0, 0);
    }
    // 6) w2 transpose
    transpose_kernel<<<dim3(DD/32, DD/32, NE), 256>>>(w2, nullptr, w2T, DD, DD);
    // 7) gate softmax
    gate_kernel<<<(BB * 32) / 256, 256>>>(combined, gate_w, gate_b, gate);
    // 8) expert GEMM2 -> t
    {
        dim3 g(DD / BN, BB / BM, NE);
        f16_gemm<<<g, 256, SMEM_BYTES>>>(h, DD, NE * DD,
                                         w2T, (long)DD * DD, DD,
                                         b2, DD, DD, 2,
                                         t, nullptr, DD, NE * DD, 0, 0);
    }
    // 9) LayerNorm + gated reduce -> out
    ln_reduce_kernel<<<BB, 256>>>(t, gate, ln_g, ln_b, out);
}

// round 9
// speedup vs baseline: 2.6010x; 1.0426x over previous
#include <cuda_runtime.h>
#include <cuda_fp16.h>
#include <math.h>
#include <cstdint>

#define BB   8192
#define DVV  768
#define NE   8
#define DD   1024
#define GG   2048

// GEMM tiling: CTA 128x256, 8 warps of 64x64, BK=64 halves, 3-stage cp.async
#define BM 128
#define BN 256
#define BK 64
#define STAGES 3
#define PADH 96                         // halves per row; 192B stride == 64 mod 128
#define STAGE_HALVES ((BM + BN) * PADH)
#define SMEM_BYTES (STAGES * STAGE_HALVES * 2)

// 32-group K-permutation: thread c's fragments for TWO k16 steps are 16B-contiguous.
// phys-in-group = 8*c + 4*kksub + 2*hi8 + b, where c=bits[1:2], kksub=bit4, hi8=bit3, b=bit0
__host__ __device__ __forceinline__ int kperm32(int k) {
    return (k & ~31) | (((k >> 1) & 3) << 3) | (((k >> 4) & 1) << 2)
         | (((k >> 3) & 1) << 1) | (k & 1);
}

// ---------------------------------------------------------------------------
// Scratch (static device globals). GEMM operands stored as k-permuted fp16.
// ---------------------------------------------------------------------------
__device__ __half g_inr[(size_t)2 * BB * DVV];
__device__ __half g_pwT[(size_t)2 * DVV * DD];
__device__ float  g_pbias[2 * DD];
__device__ __half g_w1T[(size_t)NE * GG * DD];
__device__ __half g_w2T[(size_t)NE * DD * DD];
__device__ __half g_combined[(size_t)BB * GG];
__device__ float  g_gate[BB * NE];
__device__ __half g_h[(size_t)BB * NE * DD];
__device__ float  g_t[(size_t)BB * NE * DD];

// ---------------------------------------------------------------------------
// Helpers
// ---------------------------------------------------------------------------
__device__ __forceinline__ uint32_t smem_u32(const void* p) {
    uint32_t a;
    asm("{ .reg .u64 t; cvta.to.shared.u64 t, %1; cvt.u32.u64 %0, t; }" : "=r"(a) : "l"(p));
    return a;
}
__device__ __forceinline__ void cp_async16(uint32_t dst, const void* src) {
    asm volatile("cp.async.cg.shared.global [%0], [%1], 16;" :: "r"(dst), "l"(src));
}
#define CP_COMMIT() asm volatile("cp.async.commit_group;" ::: "memory")
#define CP_WAIT(n)  asm volatile("cp.async.wait_group %0;" :: "n"(n) : "memory")

__device__ __forceinline__ void mma_f16(float& c0, float& c1, float& c2, float& c3,
                                        uint32_t a0, uint32_t a1, uint32_t a2, uint32_t a3,
                                        uint32_t b0, uint32_t b1) {
    asm volatile(
        "mma.sync.aligned.m16n8k16.row.col.f32.f16.f16.f32 "
        "{%0,%1,%2,%3}, {%4,%5,%6,%7}, {%8,%9}, {%0,%1,%2,%3};\n"
        : "+f"(c0), "+f"(c1), "+f"(c2), "+f"(c3)
        : "r"(a0), "r"(a1), "r"(a2), "r"(a3), "r"(b0), "r"(b1));
}

// ---------------------------------------------------------------------------
// fp16 tensor-core GEMM: C[m,n] = act( sum_k A[m,k]*B[n,k] + bias[n] )
// A [M,K] row-major, B [N,K] K-major, both kperm32 fp16.
// CTA 128x256, warp grid 2(m) x 4(n), warp tile 64x64, 3-stage cp.async.
// Fragment loads: one LDS.128 per row per k16-PAIR.
// mode 0: store half(v) perm cols; mode 1: half(gelu(v)) perm cols; mode 2: fp32
// ---------------------------------------------------------------------------
__global__ __launch_bounds__(256, 1)
void f16_gemm(const __half* __restrict__ A, long aBatch, int lda,
              const __half* __restrict__ B, long bBatch, int ldb,
              const float* __restrict__ bias, long biasBatch,
              int K, int mode,
              float* __restrict__ Cf, __half* __restrict__ Ch,
              long cBatch, int ldc, int colOfs, int colStride)
{
    extern __shared__ __half smem[];
    const int tid  = threadIdx.x;
    const int wid  = tid >> 5;
    const int lane = tid & 31;
    const int e    = blockIdx.z;
    const int blockRow = blockIdx.y * BM;
    const int blockCol = blockIdx.x * BN;

    A    += (long)e * aBatch;
    B    += (long)e * bBatch;
    bias += (long)e * biasBatch;
    if (Cf) Cf += (long)e * cBatch;
    if (Ch) Ch += (long)e * cBatch;
    const int cOfs = colOfs + e * colStride;

    const uint32_t smem_base = smem_u32(smem);

    // warp grid: 2 (m) x 4 (n); warp tile 64x64
    const int warpRow = (wid & 1) * 64;
    const int warpCol = (wid >> 1) * 64;
    const int groupID = lane >> 2;
    const int ctig    = lane & 3;

    float acc[4][8][4];
    #pragma unroll
    for (int i = 0; i < 4; i++)
        #pragma unroll
        for (int j = 0; j < 8; j++)
            #pragma unroll
            for (int r = 0; r < 4; r++) acc[i][j][r] = 0.0f;

    const int NC = K / BK;

    // hoisted loader bases: lm = row-in-tile, lk = 16B chunk index
    const int lm = tid >> 3, lk = tid & 7;
    const __half* aSrc = A + (long)(blockRow + lm) * lda + lk * 8;
    const __half* bSrc = B + (long)(blockCol + lm) * ldb + lk * 8;
    const uint32_t dstOfs = (uint32_t)(lm * PADH + lk * 8) * 2u;

    auto load_stage = [&](int stage, int chunk) {
        const int k0 = chunk * BK;
        const uint32_t aBase = smem_base + (uint32_t)(stage * STAGE_HALVES) * 2u + dstOfs;
        const uint32_t bBase = aBase + (uint32_t)(BM * PADH) * 2u;
        #pragma unroll
        for (int i = 0; i < 4; i++)
            cp_async16(aBase + (uint32_t)(i * 32 * PADH) * 2u,
                       aSrc + (long)(i * 32) * lda + k0);
        #pragma unroll
        for (int i = 0; i < 8; i++)
            cp_async16(bBase + (uint32_t)(i * 32 * PADH) * 2u,
                       bSrc + (long)(i * 32) * ldb + k0);
        CP_COMMIT();
    };

    #pragma unroll
    for (int s = 0; s < STAGES - 1; s++) load_stage(s, s);
    CP_WAIT(STAGES - 2);
    __syncthreads();

    for (int c = 0; c < NC; c++) {
        if (c + STAGES - 1 < NC)
            load_stage((c + STAGES - 1) % STAGES, c + STAGES - 1);

        const int stage = c % STAGES;
        const __half* As = smem + stage * STAGE_HALVES;
        const __half* Bs = As + BM * PADH;

        #pragma unroll
        for (int pr = 0; pr < 2; pr++) {          // two k16-pairs per BK=64
            const int kb = pr * 32 + 8 * ctig;    // halves within row
            uint4 alo[4], ahi[4], bv[8];
            #pragma unroll
            for (int i = 0; i < 4; i++) {
                const __half* p = As + (warpRow + i * 16 + groupID) * PADH + kb;
                alo[i] = *reinterpret_cast<const uint4*>(p);            // rows g
                ahi[i] = *reinterpret_cast<const uint4*>(p + 8 * PADH); // rows g+8
            }
            #pragma unroll
            for (int j = 0; j < 8; j++)
                bv[j] = *reinterpret_cast<const uint4*>(
                            Bs + (warpCol + j * 8 + groupID) * PADH + kb);
            #pragma unroll
            for (int i = 0; i < 4; i++)
                #pragma unroll
                for (int j = 0; j < 8; j++) {
                    mma_f16(acc[i][j][0], acc[i][j][1], acc[i][j][2], acc[i][j][3],
                            alo[i].x, ahi[i].x, alo[i].y, ahi[i].y,
                            bv[j].x, bv[j].y);
                    mma_f16(acc[i][j][0], acc[i][j][1], acc[i][j][2], acc[i][j][3],
                            alo[i].z, ahi[i].z, alo[i].w, ahi[i].w,
                            bv[j].z, bv[j].w);
                }
        }

        CP_WAIT(STAGES - 2);
        __syncthreads();
    }

    // ---- epilogue ----
    #pragma unroll
    for (int i = 0; i < 4; i++) {
        const int r0 = blockRow + warpRow + i * 16 + groupID;
        #pragma unroll
        for (int j = 0; j < 8; j++) {
            const int gc = blockCol + warpCol + j * 8 + ctig * 2;
            const float b0 = bias[gc], b1 = bias[gc + 1];
            float v0 = acc[i][j][0] + b0;
            float v1 = acc[i][j][1] + b1;
            float v2 = acc[i][j][2] + b0;
            float v3 = acc[i][j][3] + b1;
            if (mode == 2) {
                float* c0p = Cf + (long)r0 * ldc + cOfs + gc;
                float* c1p = Cf + (long)(r0 + 8) * ldc + cOfs + gc;
                *reinterpret_cast<float2*>(c0p) = make_float2(v0, v1);
                *reinterpret_cast<float2*>(c1p) = make_float2(v2, v3);
            } else {
                if (mode == 1) {
                    v0 = 0.5f * v0 * (1.0f + erff(v0 * 0.70710678118654752f));
                    v1 = 0.5f * v1 * (1.0f + erff(v1 * 0.70710678118654752f));
                    v2 = 0.5f * v2 * (1.0f + erff(v2 * 0.70710678118654752f));
                    v3 = 0.5f * v3 * (1.0f + erff(v3 * 0.70710678118654752f));
                }
                const int cp0 = kperm32(cOfs + gc);   // even k: pair stays adjacent
                *reinterpret_cast<__half2*>(Ch + (long)r0 * ldc + cp0) =
                    __floats2half2_rn(v0, v1);
                *reinterpret_cast<__half2*>(Ch + (long)(r0 + 8) * ldc + cp0) =
                    __floats2half2_rn(v2, v3);
            }
        }
    }
}

// ---------------------------------------------------------------------------
// Fused prep: convert both inputs to kperm32 fp16, pack proj biases.
// One thread = one 32-element k-group (128B read, 64B write).
// ---------------------------------------------------------------------------
__global__ void prep_kernel(const float* __restrict__ visual,
                            const float* __restrict__ text,
                            const float* __restrict__ vis_b,
                            const float* __restrict__ txt_b,
                            __half* __restrict__ inr,
                            float* __restrict__ pbias)
{
    const long nPer = (long)BB * DVV;
    long t = (long)blockIdx.x * blockDim.x + threadIdx.x;
    if (t < 2 * DD)
        pbias[t] = (t < DD) ? vis_b[t] : txt_b[t - DD];
    long i = t * 32;
    if (i >= 2 * nPer) return;
    const float* src = (i < nPer) ? (visual + i) : (text + (i - nPer));
    float lv[32];
    #pragma unroll
    for (int q = 0; q < 8; q++)
        *reinterpret_cast<float4*>(lv + q * 4) =
            *reinterpret_cast<const float4*>(src + q * 4);
    __half ph[32];
    #pragma unroll
    for (int q = 0; q < 32; q++)
        ph[kperm32(q)] = __float2half_rn(lv[q]);
    #pragma unroll
    for (int q = 0; q < 4; q++)
        *reinterpret_cast<uint4*>(inr + i + q * 8) =
            *reinterpret_cast<uint4*>(ph + q * 8);
}

// ---------------------------------------------------------------------------
// W [K,N] fp32 -> WT [N,K] fp16 kperm32; z selects source
// ---------------------------------------------------------------------------
__global__ __launch_bounds__(256)
void transpose_kernel(const float* __restrict__ W0,
                      const float* __restrict__ W1,
                      __half* __restrict__ WT, int K, int N)
{
    __shared__ float tile[32][33];
    const int e = blockIdx.z;
    const float* W = (W1 == nullptr) ? (W0 + (long)e * K * N)
                                     : (e == 0 ? W0 : W1);
    __half* WTe = WT + (long)e * K * N;
    const int n0 = blockIdx.x * 32, k0 = blockIdx.y * 32;
    const int tx = threadIdx.x & 31, ty = threadIdx.x >> 5;

    #pragma unroll
    for (int r = 0; r < 4; r++)
        tile[ty + r * 8][tx] = W[(long)(k0 + ty + r * 8) * N + n0 + tx];
    __syncthreads();
    #pragma unroll
    for (int r = 0; r < 4; r++) {
        int n = n0 + ty + r * 8, k = k0 + tx;
        WTe[(long)n * K + kperm32(k)] = __float2half_rn(tile[tx][ty + r * 8]);
    }
}

// ---------------------------------------------------------------------------
// Gate: one warp per row (combined fp16 kperm32; gw logical index)
// ---------------------------------------------------------------------------
__global__ void gate_kernel(const __half* __restrict__ combined,
                            const float* __restrict__ gw,
                            const float* __restrict__ gb,
                            float* __restrict__ gate)
{
    int warp = (blockIdx.x * blockDim.x + threadIdx.x) >> 5;
    int lane = threadIdx.x & 31;
    if (warp >= BB) return;
    const __half* row = combined + (long)warp * GG;

    float acc[NE];
    #pragma unroll
    for (int e = 0; e < NE; e++) acc[e] = 0.0f;

    for (int k = lane; k < GG; k += 32) {
        float x = __half2float(row[kperm32(k)]);
        const float4 w0 = *reinterpret_cast<const float4*>(gw + (long)k * NE);
        const float4 w1 = *reinterpret_cast<const float4*>(gw + (long)k * NE + 4);
        acc[0] = fmaf(x, w0.x, acc[0]);
        acc[1] = fmaf(x, w0.y, acc[1]);
        acc[2] = fmaf(x, w0.z, acc[2]);
        acc[3] = fmaf(x, w0.w, acc[3]);
        acc[4] = fmaf(x, w1.x, acc[4]);
        acc[5] = fmaf(x, w1.y, acc[5]);
        acc[6] = fmaf(x, w1.z, acc[6]);
        acc[7] = fmaf(x, w1.w, acc[7]);
    }
    #pragma unroll
    for (int e = 0; e < NE; e++)
        #pragma unroll
        for (int o = 16; o > 0; o >>= 1)
            acc[e] += __shfl_xor_sync(0xFFFFFFFFu, acc[e], o);

    float m = -1e30f;
    #pragma unroll
    for (int e = 0; e < NE; e++) { acc[e] += gb[e]; m = fmaxf(m, acc[e]); }
    float s = 0.0f;
    #pragma unroll
    for (int e = 0; e < NE; e++) { acc[e] = expf(acc[e] - m); s += acc[e]; }
    float inv = 1.0f / s;
    if (lane < NE) gate[(long)warp * NE + lane] = acc[lane] * inv;
}

// ---------------------------------------------------------------------------
// LayerNorm per (b,e) row + gated reduction over experts (t fp32, normal)
// ---------------------------------------------------------------------------
__global__ __launch_bounds__(256)
void ln_reduce_kernel(const float* __restrict__ t,
                      const float* __restrict__ gate,
                      const float* __restrict__ ln_g,
                      const float* __restrict__ ln_b,
                      float* __restrict__ out)
{
    const int b = blockIdx.x;
    const int tid = threadIdx.x;
    const int wid = tid >> 5, lane = tid & 31;

    __shared__ float sm_s[8];
    __shared__ float sm_ss[8];

    float o[4] = {0.f, 0.f, 0.f, 0.f};

    for (int e = 0; e < NE; e++) {
        const float* row = t + ((long)b * NE + e) * DD;
        float4 x = *reinterpret_cast<const float4*>(row + tid * 4);
        float s  = x.x + x.y + x.z + x.w;
        float ss = x.x * x.x + x.y * x.y + x.z * x.z + x.w * x.w;
        #pragma unroll
        for (int o2 = 16; o2 > 0; o2 >>= 1) {
            s  += __shfl_xor_sync(0xFFFFFFFFu, s, o2);
            ss += __shfl_xor_sync(0xFFFFFFFFu, ss, o2);
        }
        if (lane == 0) { sm_s[wid] = s; sm_ss[wid] = ss; }
        __syncthreads();
        float ts = 0.f, tss = 0.f;
        #pragma unroll
        for (int w = 0; w < 8; w++) { ts += sm_s[w]; tss += sm_ss[w]; }
        __syncthreads();

        float mu   = ts * (1.0f / DD);
        float var  = tss * (1.0f / DD) - mu * mu;
        float rstd = rsqrtf(var + 1e-5f);
        float p    = gate[(long)b * NE + e];

        const float4 g4 = *reinterpret_cast<const float4*>(ln_g + (long)e * DD + tid * 4);
        const float4 b4 = *reinterpret_cast<const float4*>(ln_b + (long)e * DD + tid * 4);
        const float* xv = &x.x;
        const float* gv = &g4.x;
        const float* bv = &b4.x;
        #pragma unroll
        for (int j = 0; j < 4; j++) {
            float n = (xv[j] - mu) * rstd;
            o[j] = fmaf(p, fmaf(n, gv[j], bv[j]), o[j]);
        }
    }
    *reinterpret_cast<float4*>(out + (long)b * DD + tid * 4) =
        make_float4(o[0], o[1], o[2], o[3]);
}

// ---------------------------------------------------------------------------
// Launch.  The 4th launch is the projection GEMM (the one ncu captures).
// ---------------------------------------------------------------------------
extern "C" void kernel_launch(void* const* d_in, const int* in_sizes, int n_in,
                              void* d_out, int out_size)
{
    const float* visual = (const float*)d_in[0];
    const float* text   = (const float*)d_in[1];
    const float* vis_w  = (const float*)d_in[2];
    const float* vis_b  = (const float*)d_in[3];
    const float* txt_w  = (const float*)d_in[4];
    const float* txt_b  = (const float*)d_in[5];
    const float* gate_w = (const float*)d_in[6];
    const float* gate_b = (const float*)d_in[7];
    const float* w1     = (const float*)d_in[8];
    const float* b1     = (const float*)d_in[9];
    const float* w2     = (const float*)d_in[10];
    const float* b2     = (const float*)d_in[11];
    const float* ln_g   = (const float*)d_in[12];
    const float* ln_b   = (const float*)d_in[13];
    float* out = (float*)d_out;

    __half *inr, *pwT, *w1T, *w2T, *combined, *h;
    float *pbias, *gate, *t;
    cudaGetSymbolAddress((void**)&inr, g_inr);
    cudaGetSymbolAddress((void**)&pwT, g_pwT);
    cudaGetSymbolAddress((void**)&pbias, g_pbias);
    cudaGetSymbolAddress((void**)&w1T, g_w1T);
    cudaGetSymbolAddress((void**)&w2T, g_w2T);
    cudaGetSymbolAddress((void**)&combined, g_combined);
    cudaGetSymbolAddress((void**)&gate, g_gate);
    cudaGetSymbolAddress((void**)&h, g_h);
    cudaGetSymbolAddress((void**)&t, g_t);

    cudaFuncSetAttribute(f16_gemm, cudaFuncAttributeMaxDynamicSharedMemorySize, SMEM_BYTES);

    // 1) w1 transpose (no deps)
    transpose_kernel<<<dim3(DD/32, GG/32, NE), 256>>>(w1, nullptr, w1T, GG, DD);
    // 2) proj weights transpose
    transpose_kernel<<<dim3(DD/32, DVV/32, 2), 256>>>(vis_w, txt_w, pwT, DVV, DD);
    // 3) input conversion + bias pack
    {
        long n = 2L * BB * DVV;
        int blocks = (int)((n / 32 + 255) / 256);
        prep_kernel<<<blocks, 256>>>(visual, text, vis_b, txt_b, inr, pbias);
    }
    // 4) batched projection (z=2) -> combined [8192, 2048]  *** profiled ***
    {
        dim3 g(DD / BN, BB / BM, 2);
        f16_gemm<<<g, 256, SMEM_BYTES>>>(inr, (long)BB * DVV, DVV,
                                         pwT, (long)DVV * DD, DVV,
                                         pbias, DD, DVV, 0,
                                         nullptr, combined, 0, GG, 0, DD);
    }
    // 5) expert GEMM1 + GELU -> h
    {
        dim3 g(DD / BN, BB / BM, NE);
        f16_gemm<<<g, 256, SMEM_BYTES>>>(combined, 0, GG,
                                         w1T, (long)GG * DD, GG,
                                         b1, DD, GG, 1,
                                         nullptr, h, DD, NE * DD, 0, 0);
    }
    // 6) w2 transpose
    transpose_kernel<<<dim3(DD/32, DD/32, NE), 256>>>(w2, nullptr, w2T, DD, DD);
    // 7) gate softmax
    gate_kernel<<<(BB * 32) / 256, 256>>>(combined, gate_w, gate_b, gate);
    // 8) expert GEMM2 -> t
    {
        dim3 g(DD / BN, BB / BM, NE);
        f16_gemm<<<g, 256, SMEM_BYTES>>>(h, DD, NE * DD,
                                         w2T, (long)DD * DD, DD,
                                         b2, DD, DD, 2,
                                         t, nullptr, DD, NE * DD, 0, 0);
    }
    // 9) LayerNorm + gated reduce -> out
    ln_reduce_kernel<<<BB, 256>>>(t, gate, ln_g, ln_b, out);
}